// round 3
// baseline (speedup 1.0000x reference)
#include <cuda_runtime.h>

// A [B=256, d=512, d=512] fp32, mask [16, 512] fp32, regimes [B] int32.
// Output: 1 float scalar.
#define D 512
#define D4 (D / 4)          // 128 float4 groups per row
#define ROWS_PER_BLK 64     // 8 row-chunks per batch
#define NBLK 2048           // (512/64) * 256

__device__ float g_part[NBLK];

__global__ void __launch_bounds__(256)
k_reduce(const float* __restrict__ A,
         const float* __restrict__ mask,
         const int* __restrict__ regimes,
         int n_regimes) {
    const int b = blockIdx.y;
    const int e = regimes[b];
    const bool valid = (e < n_regimes);
    const int ec = e < 0 ? 0 : (e >= n_regimes ? n_regimes - 1 : e);

    __shared__ float4 smask[D4];
    const int tid = threadIdx.x;
    if (tid < D4) {
        float4 m = reinterpret_cast<const float4*>(mask + (long long)ec * D)[tid];
        if (!valid) m = make_float4(0.f, 0.f, 0.f, 0.f);
        smask[tid] = m;
    }
    __syncthreads();

    const int j4   = tid & (D4 - 1);   // column group
    const int rsub = tid >> 7;         // 0/1 row interleave
    const float4 m = smask[j4];
    const bool live = (m.x != 0.f) || (m.y != 0.f) || (m.z != 0.f) || (m.w != 0.f);

    float acc = 0.f;
    if (live) {
        const float4* base = reinterpret_cast<const float4*>(
            A + ((long long)b * D + (long long)blockIdx.x * ROWS_PER_BLK + rsub) * D) + j4;
        // 32 independent loads, fully unrolled -> front-batched LDG.128, high MLP
        float4 a[32];
        #pragma unroll
        for (int i = 0; i < 32; i++) a[i] = base[(long long)i * 2 * D4];
        #pragma unroll
        for (int i = 0; i < 32; i++)
            acc += a[i].x * m.x + a[i].y * m.y + a[i].z * m.z + a[i].w * m.w;
    }

    // block reduction
    #pragma unroll
    for (int o = 16; o > 0; o >>= 1) acc += __shfl_down_sync(0xffffffffu, acc, o);
    __shared__ float warpsum[8];
    if ((tid & 31) == 0) warpsum[tid >> 5] = acc;
    __syncthreads();
    if (tid < 8) {
        float v = warpsum[tid];
        #pragma unroll
        for (int o = 4; o > 0; o >>= 1) v += __shfl_down_sync(0xffu, v, o);
        if (tid == 0) g_part[blockIdx.y * gridDim.x + blockIdx.x] = v;
    }
}

__global__ void __launch_bounds__(256)
k_final(const float* __restrict__ mask,
        const int* __restrict__ regimes,
        int B, int n_regimes, float* __restrict__ out) {
    const int tid = threadIdx.x;

    // sum partials in double
    double lsum = 0.0;
    #pragma unroll
    for (int i = tid; i < NBLK; i += 256) lsum += (double)g_part[i];

    // count = sum of gathered mask rows
    float c = 0.f;
    for (int b = tid; b < B; b += 256) {
        int e = regimes[b];
        if (e < n_regimes) {
            const float* mr = mask + (long long)(e < 0 ? 0 : e) * D;
            float s = 0.f;
            #pragma unroll 8
            for (int j = 0; j < D; j++) s += mr[j];
            c += s;
        }
    }

    #pragma unroll
    for (int o = 16; o > 0; o >>= 1) {
        lsum += __shfl_down_sync(0xffffffffu, lsum, o);
        c    += __shfl_down_sync(0xffffffffu, c, o);
    }
    __shared__ double wsum[8];
    __shared__ float  wcnt[8];
    if ((tid & 31) == 0) { wsum[tid >> 5] = lsum; wcnt[tid >> 5] = c; }
    __syncthreads();
    if (tid == 0) {
        double loss = 0.0; float count = 0.f;
        #pragma unroll
        for (int w = 0; w < 8; w++) { loss += wsum[w]; count += wcnt[w]; }
        float lf = (float)loss;
        out[0] = (count > 0.f) ? (lf / count) : lf;   // INTERVENTION_STRENGTH = 1.0
    }
}

extern "C" void kernel_launch(void* const* d_in, const int* in_sizes, int n_in,
                              void* d_out, int out_size) {
    const float* A    = (const float*)d_in[0];
    const float* mask = (const float*)d_in[1];
    const int*   reg  = (const int*)d_in[2];

    const int B = in_sizes[2];                 // 256
    const int n_regimes = in_sizes[1] / D;     // 16

    dim3 grid(D / ROWS_PER_BLK, B);            // (8, 256) = 2048 blocks
    k_reduce<<<grid, 256>>>(A, mask, reg, n_regimes);
    k_final<<<1, 256>>>(mask, reg, B, n_regimes, (float*)d_out);
}

// round 4
// speedup vs baseline: 1.6272x; 1.6272x over previous
#include <cuda_runtime.h>

// A [B=256, d=512, d=512] fp32, mask [16, 512] fp32, regimes [B] int32.
// Output: 1 float scalar.
#define D 512
#define D4 (D / 4)          // 128 float4 groups per row
#define ROWS_PER_BLK 64     // 8 row-chunks per batch
#define NBLK 2048           // (512/64) * 256
#define MAX_REG 64          // upper bound on n_regimes we stage in smem

__device__ float g_part[NBLK];

__global__ void __launch_bounds__(256)
k_reduce(const float* __restrict__ A,
         const float* __restrict__ mask,
         const int* __restrict__ regimes,
         int n_regimes) {
    const int b = blockIdx.y;
    const int e = regimes[b];
    const bool valid = (e < n_regimes);
    const int ec = e < 0 ? 0 : (e >= n_regimes ? n_regimes - 1 : e);

    __shared__ float4 smask[D4];
    const int tid = threadIdx.x;
    if (tid < D4) {
        float4 m = reinterpret_cast<const float4*>(mask + (long long)ec * D)[tid];
        if (!valid) m = make_float4(0.f, 0.f, 0.f, 0.f);
        smask[tid] = m;
    }
    __syncthreads();

    const int j4   = tid & (D4 - 1);   // column group
    const int rsub = tid >> 7;         // 0/1 row interleave
    const float4 m = smask[j4];
    const bool live = (m.x != 0.f) || (m.y != 0.f) || (m.z != 0.f) || (m.w != 0.f);

    float acc = 0.f;
    if (live) {
        const float4* base = reinterpret_cast<const float4*>(
            A + ((long long)b * D + (long long)blockIdx.x * ROWS_PER_BLK + rsub) * D) + j4;
        #pragma unroll 8
        for (int i = 0; i < ROWS_PER_BLK / 2; i++) {
            float4 a = base[(long long)i * 2 * D4];
            acc += a.x * m.x + a.y * m.y + a.z * m.z + a.w * m.w;
        }
    }

    // block reduction
    #pragma unroll
    for (int o = 16; o > 0; o >>= 1) acc += __shfl_down_sync(0xffffffffu, acc, o);
    __shared__ float warpsum[8];
    if ((tid & 31) == 0) warpsum[tid >> 5] = acc;
    __syncthreads();
    if (tid < 8) {
        float v = warpsum[tid];
        #pragma unroll
        for (int o = 4; o > 0; o >>= 1) v += __shfl_down_sync(0xffu, v, o);
        if (tid == 0) g_part[blockIdx.y * gridDim.x + blockIdx.x] = v;
    }
}

__global__ void __launch_bounds__(256)
k_final(const float* __restrict__ mask,
        const int* __restrict__ regimes,
        int B, int n_regimes, float* __restrict__ out) {
    const int tid  = threadIdx.x;
    const int wid  = tid >> 5;
    const int lane = tid & 31;

    __shared__ float s_rowsum[MAX_REG];
    __shared__ double wsum[8];
    __shared__ float  wcnt[8];

    // ---- Phase 1: per-regime mask row sums (parallel, coalesced) ----
    // warp w handles regimes w, w+8, ... ; each lane sums 16 strided elements.
    for (int r = wid; r < n_regimes && r < MAX_REG; r += 8) {
        const float* mr = mask + (long long)r * D;
        float s = 0.f;
        #pragma unroll
        for (int j = 0; j < D / 32; j++) s += mr[j * 32 + lane];
        #pragma unroll
        for (int o = 16; o > 0; o >>= 1) s += __shfl_down_sync(0xffffffffu, s, o);
        if (lane == 0) s_rowsum[r] = s;
    }
    __syncthreads();

    // ---- Phase 2: loss partials (double) + count via rowsum gather ----
    double lsum = 0.0;
    #pragma unroll 4
    for (int i = tid; i < NBLK; i += 256) lsum += (double)g_part[i];

    float c = 0.f;
    for (int b = tid; b < B; b += 256) {
        int e = regimes[b];
        if (e < n_regimes) c += s_rowsum[(e < 0 ? 0 : e)];
    }

    #pragma unroll
    for (int o = 16; o > 0; o >>= 1) {
        lsum += __shfl_down_sync(0xffffffffu, lsum, o);
        c    += __shfl_down_sync(0xffffffffu, c, o);
    }
    if (lane == 0) { wsum[wid] = lsum; wcnt[wid] = c; }
    __syncthreads();
    if (tid == 0) {
        double loss = 0.0; float count = 0.f;
        #pragma unroll
        for (int w = 0; w < 8; w++) { loss += wsum[w]; count += wcnt[w]; }
        float lf = (float)loss;
        out[0] = (count > 0.f) ? (lf / count) : lf;   // INTERVENTION_STRENGTH = 1.0
    }
}

extern "C" void kernel_launch(void* const* d_in, const int* in_sizes, int n_in,
                              void* d_out, int out_size) {
    const float* A    = (const float*)d_in[0];
    const float* mask = (const float*)d_in[1];
    const int*   reg  = (const int*)d_in[2];

    const int B = in_sizes[2];                 // 256
    const int n_regimes = in_sizes[1] / D;     // 16

    dim3 grid(D / ROWS_PER_BLK, B);            // (8, 256) = 2048 blocks
    k_reduce<<<grid, 256>>>(A, mask, reg, n_regimes);
    k_final<<<1, 256>>>(mask, reg, B, n_regimes, (float*)d_out);
}

// round 5
// speedup vs baseline: 1.6458x; 1.0114x over previous
#include <cuda_runtime.h>

// A [B=256, d=512, d=512] fp32, mask [16, 512] fp32, regimes [B] int32.
// Output: 1 float scalar.
#define D 512
#define D4 (D / 4)          // 128 float4 groups per row
#define ROWS_PER_BLK 64     // 8 row-chunks per batch
#define NBLK 2048           // (512/64) * 256
#define MAX_REG 64
#define MAX_B 4096

__device__ float    g_part[NBLK];
__device__ unsigned g_cnt;            // zero-initialized; reset to 0 by the last block

__global__ void __launch_bounds__(256)
k_reduce(const float* __restrict__ A,
         const float* __restrict__ mask,
         const int* __restrict__ regimes,
         int B, int n_regimes, float* __restrict__ out) {
    const int tid  = threadIdx.x;
    const int wid  = tid >> 5;
    const int lane = tid & 31;
    const int b    = blockIdx.y;

    const int e = regimes[b];
    const bool valid = (e < n_regimes);
    const int ec = e < 0 ? 0 : (e >= n_regimes ? n_regimes - 1 : e);

    __shared__ float4 smask[D4];
    if (tid < D4) {
        float4 m = reinterpret_cast<const float4*>(mask + (long long)ec * D)[tid];
        if (!valid) m = make_float4(0.f, 0.f, 0.f, 0.f);
        smask[tid] = m;
    }
    __syncthreads();

    const int j4   = tid & (D4 - 1);
    const int rsub = tid >> 7;
    const float4 m = smask[j4];
    const bool live = (m.x != 0.f) || (m.y != 0.f) || (m.z != 0.f) || (m.w != 0.f);

    float acc = 0.f;
    if (live) {
        const float4* base = reinterpret_cast<const float4*>(
            A + ((long long)b * D + (long long)blockIdx.x * ROWS_PER_BLK + rsub) * D) + j4;
        #pragma unroll 8
        for (int i = 0; i < ROWS_PER_BLK / 2; i++) {
            float4 a = base[(long long)i * 2 * D4];
            acc += a.x * m.x + a.y * m.y + a.z * m.z + a.w * m.w;
        }
    }

    // block reduction
    #pragma unroll
    for (int o = 16; o > 0; o >>= 1) acc += __shfl_down_sync(0xffffffffu, acc, o);
    __shared__ float warpsum[8];
    if (lane == 0) warpsum[wid] = acc;
    __syncthreads();

    __shared__ bool s_last;
    if (tid == 0) {
        float v = 0.f;
        #pragma unroll
        for (int w = 0; w < 8; w++) v += warpsum[w];
        g_part[blockIdx.y * gridDim.x + blockIdx.x] = v;
        __threadfence();
        unsigned old = atomicAdd(&g_cnt, 1u);
        s_last = (old == NBLK - 1u);
    }
    __syncthreads();
    if (!s_last) return;

    // ================= fused finalization (last block only) =================
    __shared__ float  s_rowsum[MAX_REG];
    __shared__ double wsum[8];
    __shared__ float  wcnt[8];

    // per-regime mask row sums (L2-resident)
    for (int r = wid; r < n_regimes && r < MAX_REG; r += 8) {
        const float* mr = mask + (long long)r * D;
        float s = 0.f;
        #pragma unroll
        for (int j = 0; j < D / 32; j++) s += __ldcg(mr + j * 32 + lane);
        #pragma unroll
        for (int o = 16; o > 0; o >>= 1) s += __shfl_down_sync(0xffffffffu, s, o);
        if (lane == 0) s_rowsum[r] = s;
    }
    __syncthreads();

    double lsum = 0.0;
    #pragma unroll 4
    for (int i = tid; i < NBLK; i += 256) lsum += (double)__ldcg(&g_part[i]);

    float c = 0.f;
    for (int bb = tid; bb < B && bb < MAX_B; bb += 256) {
        int ee = __ldcg(&regimes[bb]);
        if (ee < n_regimes) c += s_rowsum[(ee < 0 ? 0 : ee)];
    }

    #pragma unroll
    for (int o = 16; o > 0; o >>= 1) {
        lsum += __shfl_down_sync(0xffffffffu, lsum, o);
        c    += __shfl_down_sync(0xffffffffu, c, o);
    }
    if (lane == 0) { wsum[wid] = lsum; wcnt[wid] = c; }
    __syncthreads();
    if (tid == 0) {
        double loss = 0.0; float count = 0.f;
        #pragma unroll
        for (int w = 0; w < 8; w++) { loss += wsum[w]; count += wcnt[w]; }
        float lf = (float)loss;
        out[0] = (count > 0.f) ? (lf / count) : lf;   // INTERVENTION_STRENGTH = 1.0
        g_cnt = 0;                                    // reset for next graph replay
    }
}

extern "C" void kernel_launch(void* const* d_in, const int* in_sizes, int n_in,
                              void* d_out, int out_size) {
    const float* A    = (const float*)d_in[0];
    const float* mask = (const float*)d_in[1];
    const int*   reg  = (const int*)d_in[2];

    const int B = in_sizes[2];                 // 256
    const int n_regimes = in_sizes[1] / D;     // 16

    dim3 grid(D / ROWS_PER_BLK, B);            // (8, 256) = 2048 blocks
    k_reduce<<<grid, 256>>>(A, mask, reg, B, n_regimes, (float*)d_out);
}

// round 6
// speedup vs baseline: 1.7210x; 1.0457x over previous
#include <cuda_runtime.h>

// A [B=256, d=512, d=512] fp32, mask [16, 512] fp32, regimes [B] int32.
// Output: 1 float scalar.
#define D 512
#define D4 (D / 4)          // 128 float4 groups per row
#define ROWS_PER_BLK 128    // 4 row-chunks per batch -> 1024 blocks = ONE wave
#define NBLK 1024           // (512/128) * 256
#define MAX_REG 64
#define MAX_B 4096

__device__ float    g_part[NBLK];
__device__ unsigned g_cnt;            // zero-initialized; reset to 0 by the last block

__global__ void __launch_bounds__(256)
k_reduce(const float* __restrict__ A,
         const float* __restrict__ mask,
         const int* __restrict__ regimes,
         int B, int n_regimes, float* __restrict__ out) {
    const int tid  = threadIdx.x;
    const int wid  = tid >> 5;
    const int lane = tid & 31;
    const int b    = blockIdx.y;

    const int e = regimes[b];
    const bool valid = (e < n_regimes);
    const int ec = e < 0 ? 0 : (e >= n_regimes ? n_regimes - 1 : e);

    __shared__ float4 smask[D4];
    if (tid < D4) {
        float4 m = reinterpret_cast<const float4*>(mask + (long long)ec * D)[tid];
        if (!valid) m = make_float4(0.f, 0.f, 0.f, 0.f);
        smask[tid] = m;
    }
    __syncthreads();

    const int j4   = tid & (D4 - 1);   // column group
    const int rsub = tid >> 7;         // 0/1 row interleave
    const float4 m = smask[j4];
    const bool live = (m.x != 0.f) || (m.y != 0.f) || (m.z != 0.f) || (m.w != 0.f);

    float acc = 0.f;
    if (live) {
        const float4* base = reinterpret_cast<const float4*>(
            A + ((long long)b * D + (long long)blockIdx.x * ROWS_PER_BLK + rsub) * D) + j4;
        #pragma unroll 8
        for (int i = 0; i < ROWS_PER_BLK / 2; i++) {
            float4 a = base[(long long)i * 2 * D4];
            acc += a.x * m.x + a.y * m.y + a.z * m.z + a.w * m.w;
        }
    }

    // block reduction
    #pragma unroll
    for (int o = 16; o > 0; o >>= 1) acc += __shfl_down_sync(0xffffffffu, acc, o);
    __shared__ float warpsum[8];
    if (lane == 0) warpsum[wid] = acc;
    __syncthreads();

    __shared__ bool s_last;
    if (tid == 0) {
        float v = 0.f;
        #pragma unroll
        for (int w = 0; w < 8; w++) v += warpsum[w];
        g_part[blockIdx.y * gridDim.x + blockIdx.x] = v;
        __threadfence();
        unsigned old = atomicAdd(&g_cnt, 1u);
        s_last = (old == NBLK - 1u);
    }
    __syncthreads();
    if (!s_last) return;

    // ================= fused finalization (last block only) =================
    __shared__ float  s_rowsum[MAX_REG];
    __shared__ double wsum[8];
    __shared__ float  wcnt[8];

    // per-regime mask row sums (L2-resident)
    for (int r = wid; r < n_regimes && r < MAX_REG; r += 8) {
        const float* mr = mask + (long long)r * D;
        float s = 0.f;
        #pragma unroll
        for (int j = 0; j < D / 32; j++) s += __ldcg(mr + j * 32 + lane);
        #pragma unroll
        for (int o = 16; o > 0; o >>= 1) s += __shfl_down_sync(0xffffffffu, s, o);
        if (lane == 0) s_rowsum[r] = s;
    }
    __syncthreads();

    double lsum = 0.0;
    #pragma unroll 4
    for (int i = tid; i < NBLK; i += 256) lsum += (double)__ldcg(&g_part[i]);

    float c = 0.f;
    for (int bb = tid; bb < B && bb < MAX_B; bb += 256) {
        int ee = __ldcg(&regimes[bb]);
        if (ee < n_regimes) c += s_rowsum[(ee < 0 ? 0 : ee)];
    }

    #pragma unroll
    for (int o = 16; o > 0; o >>= 1) {
        lsum += __shfl_down_sync(0xffffffffu, lsum, o);
        c    += __shfl_down_sync(0xffffffffu, c, o);
    }
    if (lane == 0) { wsum[wid] = lsum; wcnt[wid] = c; }
    __syncthreads();
    if (tid == 0) {
        double loss = 0.0; float count = 0.f;
        #pragma unroll
        for (int w = 0; w < 8; w++) { loss += wsum[w]; count += wcnt[w]; }
        float lf = (float)loss;
        out[0] = (count > 0.f) ? (lf / count) : lf;   // INTERVENTION_STRENGTH = 1.0
        g_cnt = 0;                                    // reset for next graph replay
    }
}

extern "C" void kernel_launch(void* const* d_in, const int* in_sizes, int n_in,
                              void* d_out, int out_size) {
    const float* A    = (const float*)d_in[0];
    const float* mask = (const float*)d_in[1];
    const int*   reg  = (const int*)d_in[2];

    const int B = in_sizes[2];                 // 256
    const int n_regimes = in_sizes[1] / D;     // 16

    dim3 grid(D / ROWS_PER_BLK, B);            // (4, 256) = 1024 blocks, single wave
    k_reduce<<<grid, 256>>>(A, mask, reg, B, n_regimes, (float*)d_out);
}